// round 17
// baseline (speedup 1.0000x reference)
#include <cuda_runtime.h>
#include <cuda_fp16.h>
#include <mma.h>
#include <math.h>

using namespace nvcuda;

#define NN   8192
#define FIN  128
#define FOUT 64
#define HH   4
#define MAXE 512
#define ALPHA 0.2f
#define BM   64

// Scratch (allocation-free rule: __device__ globals)
__device__ __half g_Whh[HH * NN * FOUT];  // fp16 Wh, 4 MB, L2-resident
__device__ float  g_f1p[NN * HH];         // f1 packed per node
__device__ float  g_f2p[NN * HH];         // f2 packed per node

// ---------------------------------------------------------------------------
// Kernel 1: Wh[h] = x @ W[h] on TENSOR CORES (wmma m16n16k16, fp16->fp32).
// BM=64 rows/CTA, 128 threads (4 warps: warp w owns rows w*16..w*16+15).
// Epilogue: f1/f2 dots + fp16 Wh store. PDL trigger at entry.
// ---------------------------------------------------------------------------
__global__ __launch_bounds__(128) void proj_kernel(const float* __restrict__ x,
                                                   const float* __restrict__ W,
                                                   const float* __restrict__ a1,
                                                   const float* __restrict__ a2) {
#if __CUDA_ARCH__ >= 900
    cudaTriggerProgrammaticLaunchCompletion();
#endif
    __shared__ __half xs[BM][FIN];     // 16 KB   x tile, fp16
    __shared__ __half wsh[FIN][FOUT];  // 16 KB   W (this head), fp16
    __shared__ float  cs[BM][FOUT];    // 16 KB   fp32 result tile

    const int rb  = blockIdx.x * BM;
    const int h   = blockIdx.y;
    const int tid = threadIdx.x;
    const int w   = tid >> 5;
    const int lane = tid & 31;
    const float* Wp = W + (size_t)h * FIN * FOUT;

    // ---- load + convert x tile (64x128) and W (128x64) to fp16 smem ----
    for (int idx = tid; idx < BM * (FIN / 4); idx += 128) {
        int r  = idx >> 5;            // 32 float4 per row
        int c4 = idx & 31;
        float4 v = *(const float4*)&x[(size_t)(rb + r) * FIN + c4 * 4];
        __half2 p0 = __floats2half2_rn(v.x, v.y);
        __half2 p1 = __floats2half2_rn(v.z, v.w);
        *(uint2*)&xs[r][c4 * 4] = make_uint2(*(unsigned*)&p0, *(unsigned*)&p1);
    }
    for (int idx = tid; idx < FIN * (FOUT / 4); idx += 128) {
        int r  = idx >> 4;            // 16 float4 per row
        int c4 = idx & 15;
        float4 v = *(const float4*)&Wp[(size_t)r * FOUT + c4 * 4];
        __half2 p0 = __floats2half2_rn(v.x, v.y);
        __half2 p1 = __floats2half2_rn(v.z, v.w);
        *(uint2*)&wsh[r][c4 * 4] = make_uint2(*(unsigned*)&p0, *(unsigned*)&p1);
    }
    __syncthreads();

    // ---- wmma: warp w computes rows [w*16, w*16+16) x all 64 cols ----
    {
        wmma::fragment<wmma::accumulator, 16, 16, 16, float> acc[4];
#pragma unroll
        for (int n = 0; n < 4; ++n) wmma::fill_fragment(acc[n], 0.0f);
#pragma unroll
        for (int k = 0; k < FIN / 16; ++k) {
            wmma::fragment<wmma::matrix_a, 16, 16, 16, __half, wmma::row_major> af;
            wmma::load_matrix_sync(af, &xs[w * 16][k * 16], FIN);
#pragma unroll
            for (int n = 0; n < 4; ++n) {
                wmma::fragment<wmma::matrix_b, 16, 16, 16, __half, wmma::row_major> bf;
                wmma::load_matrix_sync(bf, &wsh[k * 16][n * 16], FOUT);
                wmma::mma_sync(acc[n], af, bf, acc[n]);
            }
        }
#pragma unroll
        for (int n = 0; n < 4; ++n)
            wmma::store_matrix_sync(&cs[w * 16][n * 16], acc[n], FOUT, wmma::mem_row_major);
    }
    __syncthreads();

    // ---- epilogue: 2 threads per row (32 cols each): f1/f2 + fp16 store ----
    {
        const int r  = tid >> 1;          // row 0..63
        const int hx = tid & 1;           // col half
        const int c0 = hx * 32;
        float p1 = 0.f, p2 = 0.f;
        const float* crow = &cs[r][c0];
        const float* a1p  = &a1[h * FOUT + c0];
        const float* a2p  = &a2[h * FOUT + c0];
#pragma unroll
        for (int c = 0; c < 32; ++c) {
            float v = crow[c];
            p1 += v * a1p[c];
            p2 += v * a2p[c];
        }
        p1 += __shfl_xor_sync(0xffffffffu, p1, 1);
        p2 += __shfl_xor_sync(0xffffffffu, p2, 1);
        int row = rb + r;
        if (hx == 0) {
            g_f1p[row * HH + h] = p1;
            g_f2p[row * HH + h] = p2;
        }
        // pack 32 fp32 -> 32 half (4 x 16B stores)
        __half* dst = &g_Whh[((size_t)h * NN + row) * FOUT + c0];
#pragma unroll
        for (int qb = 0; qb < 4; ++qb) {
            __half2 hp[4];
#pragma unroll
            for (int k = 0; k < 4; ++k)
                hp[k] = __floats2half2_rn(crow[qb * 8 + k * 2], crow[qb * 8 + k * 2 + 1]);
            *(uint4*)(dst + qb * 8) = *(uint4*)hp;
        }
    }
}

// ---------------------------------------------------------------------------
// Kernel 2: per-row fused masked softmax + aggregation + ELU (R15 champion,
// frozen). Arithmetic mask build, ffs compaction, no-max softmax, fp16
// warp-per-edge gather. PDL sync before consuming proj outputs.
// ---------------------------------------------------------------------------
__global__ __launch_bounds__(256) void attn_kernel(const float* __restrict__ adj,
                                                   float* __restrict__ out) {
    const int i    = blockIdx.x;
    const int tid  = threadIdx.x;
    const int lane = tid & 31;
    const int w    = tid >> 5;

    __shared__ int   s_ej[MAXE];
    __shared__ float s_evp[MAXE][HH];     // exp weights, heads adjacent
    __shared__ int   s_wt[8];
    __shared__ float s_psum[8][HH];
    __shared__ float s_part[8][32][9];    // padded partial accumulators

    // ---- phase 1: arithmetic edge-mask build (adj in {0.0, 1.0}) ----
    const float* arow = adj + (size_t)i * NN;
    float mlo = 0.f, mhi = 0.f;
#pragma unroll
    for (int q = 0; q < 8; ++q) {
        float4 v = __ldcs((const float4*)&arow[q * 1024 + tid * 4]);
        float nib = v.x;
        nib = fmaf(v.y, 2.f, nib);
        nib = fmaf(v.z, 4.f, nib);
        nib = fmaf(v.w, 8.f, nib);
        if (q < 4) mlo = fmaf(nib, (float)(1u << (q * 4)), mlo);
        else       mhi = fmaf(nib, (float)(1u << ((q - 4) * 4)), mhi);
    }
    unsigned mask = (unsigned)__float2uint_rn(mlo)
                  | ((unsigned)__float2uint_rn(mhi) << 16);
    int cnt = __popc(mask);

    // ---- phase 2: scan of counts ----
    int inc = cnt;
#pragma unroll
    for (int off = 1; off < 32; off <<= 1) {
        int v = __shfl_up_sync(0xffffffffu, inc, off);
        if (lane >= off) inc += v;
    }
    if (lane == 31) s_wt[w] = inc;
    __syncthreads();
    int base = 0, total = 0;
#pragma unroll
    for (int k = 0; k < 8; ++k) {
        int t = s_wt[k];
        if (k < w) base += t;
        total += t;
    }
    if (total > MAXE) total = MAXE;
    int pos = base + inc - cnt;

    // ---- phase 3: compact edge indices (iterate set bits only) ----
    {
        unsigned m = mask;
        const int jb = tid << 2;
        while (m) {
            int b = __ffs(m) - 1;
            m &= m - 1;
            if (pos < MAXE) s_ej[pos] = ((b >> 2) << 10) + jb + (b & 3);
            ++pos;
        }
    }

    // ---- wait for proj outputs (f1p/f2p/Whh) ----
#if __CUDA_ARCH__ >= 900
    cudaGridDependencySynchronize();
#endif
    __syncthreads();

    // ---- phase 4: w = exp(lrelu(f1_i + f2_j)) fused, single dense pass ----
    float4 f1v = *(const float4*)&g_f1p[i * HH];
    float mysum[HH] = {0.f, 0.f, 0.f, 0.f};
    for (int p = tid; p < total; p += 256) {
        int j = s_ej[p];
        float4 f2v = *(const float4*)&g_f2p[j * HH];
        float e0 = f1v.x + f2v.x; e0 = (e0 > 0.f) ? e0 : ALPHA * e0; e0 = __expf(e0);
        float e1 = f1v.y + f2v.y; e1 = (e1 > 0.f) ? e1 : ALPHA * e1; e1 = __expf(e1);
        float e2 = f1v.z + f2v.z; e2 = (e2 > 0.f) ? e2 : ALPHA * e2; e2 = __expf(e2);
        float e3 = f1v.w + f2v.w; e3 = (e3 > 0.f) ? e3 : ALPHA * e3; e3 = __expf(e3);
        *(float4*)s_evp[p] = make_float4(e0, e1, e2, e3);
        mysum[0] += e0; mysum[1] += e1; mysum[2] += e2; mysum[3] += e3;
    }
#pragma unroll
    for (int h = 0; h < HH; ++h)
#pragma unroll
        for (int off = 16; off; off >>= 1)
            mysum[h] += __shfl_xor_sync(0xffffffffu, mysum[h], off);
    if (lane == 0)
#pragma unroll
        for (int h = 0; h < HH; ++h) s_psum[w][h] = mysum[h];
    __syncthreads();

    // ---- phase 5: aggregation. warp = edge slice, lane = (head, chunk) ----
    {
        const int h = lane >> 3;      // head
        const int c = lane & 7;       // 8-half feature chunk
        const __half* whb = g_Whh + (size_t)h * NN * FOUT + c * 8;
        float acc[8] = {};
        for (int p = w; p < total; p += 8) {
            int   j  = s_ej[p];
            float wv = s_evp[p][h];
            uint4 raw = *(const uint4*)&whb[(size_t)j * FOUT];
            __half2* hp = (__half2*)&raw;
            float2 f0 = __half22float2(hp[0]);
            float2 f1 = __half22float2(hp[1]);
            float2 f2 = __half22float2(hp[2]);
            float2 f3 = __half22float2(hp[3]);
            acc[0] += wv * f0.x; acc[1] += wv * f0.y;
            acc[2] += wv * f1.x; acc[3] += wv * f1.y;
            acc[4] += wv * f2.x; acc[5] += wv * f2.y;
            acc[6] += wv * f3.x; acc[7] += wv * f3.y;
        }
#pragma unroll
        for (int f = 0; f < 8; ++f) s_part[w][lane][f] = acc[f];
    }
    __syncthreads();

    // ---- phase 6: reduce 8 slices, normalize, ELU, store ----
    {
        const int g  = tid >> 3;      // group = h*8 + chunk  (0..31)
        const int f  = tid & 7;
        const int h  = tid >> 6;
        float gsum = s_psum[0][h];
#pragma unroll
        for (int k = 1; k < 8; ++k) gsum += s_psum[k][h];
        float v = 0.f;
#pragma unroll
        for (int k = 0; k < 8; ++k) v += s_part[k][g][f];
        v /= gsum;
        v = (v > 0.f) ? v : expm1f(v);   // ELU
        out[(size_t)i * (HH * FOUT) + tid] = v;   // tid == h*64 + chunk*8 + f
    }
}

// ---------------------------------------------------------------------------
extern "C" void kernel_launch(void* const* d_in, const int* in_sizes, int n_in,
                              void* d_out, int out_size) {
    const float* x   = (const float*)d_in[0];   // [8192,128]
    const float* adj = (const float*)d_in[1];   // [8192,8192]
    const float* W   = (const float*)d_in[2];   // [4,128,64]
    const float* a1  = (const float*)d_in[3];   // [4,64]
    const float* a2  = (const float*)d_in[4];   // [4,64]
    float* out = (float*)d_out;                 // [8192, 256]

    proj_kernel<<<dim3(NN / BM, HH), 128>>>(x, W, a1, a2);

    // attn via PDL: launches while proj runs; internal grid-dependency sync
    // before consuming proj outputs.
    cudaLaunchConfig_t cfg = {};
    cfg.gridDim  = dim3(NN);
    cfg.blockDim = dim3(256);
    cfg.dynamicSmemBytes = 0;
    cfg.stream = 0;
    cudaLaunchAttribute at[1];
    at[0].id = cudaLaunchAttributeProgrammaticStreamSerialization;
    at[0].val.programmaticStreamSerializationAllowed = 1;
    cfg.attrs = at;
    cfg.numAttrs = 1;
    cudaLaunchKernelEx(&cfg, attn_kernel, adj, out);
}